// round 15
// baseline (speedup 1.0000x reference)
#include <cuda_runtime.h>
#include <cuda_fp16.h>
#include <cstdint>

#define NB 2
#define NC 256
#define NL 4096

// ---------------------------------------------------------------------------
// Scratch
// ---------------------------------------------------------------------------
__device__ __half g_q [NB * NL * NC];       // normalized trg, [B][L][C] K-major
__device__ __half g_ks[NB * NL * NC];
__device__ __half g_kr[NB * NL * NC];
__device__ __half g_v [4ull * 160 * NL];    // padded V banks per z
__device__ float  g_opart[4ull * 8 * 160 * NL];  // partial O [z][h<8][ch][i]
__device__ float  g_rsp  [4 * 8 * NL];           // partial rsum [z][h][i]

// ---------------------------------------------------------------------------
// helpers
// ---------------------------------------------------------------------------
__device__ __forceinline__ uint32_t smem_u32(const void* p) {
    uint32_t a;
    asm("{ .reg .u64 t; cvta.to.shared.u64 t, %1; cvt.u32.u64 %0, t; }" : "=r"(a) : "l"(p));
    return a;
}

#define CPA16(dst, src) asm volatile("cp.async.cg.shared.global [%0], [%1], 16;" :: "r"(dst), "l"(src))
#define CPCOMMIT()      asm volatile("cp.async.commit_group;" ::: "memory")
#define CPWAIT(n)       asm volatile("cp.async.wait_group %0;" :: "n"(n) : "memory")

#define LDSM_X4(R0, R1, R2, R3, A) \
    asm volatile("ldmatrix.sync.aligned.m8n8.x4.shared.b16 {%0,%1,%2,%3}, [%4];" \
                 : "=r"(R0), "=r"(R1), "=r"(R2), "=r"(R3) : "r"(A))

// byte offset of the 16B group (m, f) in a 128B-row tile, row-XOR swizzled
__device__ __forceinline__ uint32_t swzb(int m, int f) {
    return ((uint32_t)m << 7) + (uint32_t)(((f) ^ (m & 7)) << 4);
}

__device__ __forceinline__ void mma16(float* d, const uint32_t* a, uint32_t b0, uint32_t b1) {
    asm volatile(
        "mma.sync.aligned.m16n8k16.row.col.f32.f16.f16.f32 "
        "{%0,%1,%2,%3}, {%4,%5,%6,%7}, {%8,%9}, {%0,%1,%2,%3};"
        : "+f"(d[0]), "+f"(d[1]), "+f"(d[2]), "+f"(d[3])
        : "r"(a[0]), "r"(a[1]), "r"(a[2]), "r"(a[3]), "r"(b0), "r"(b1));
}

// ---------------------------------------------------------------------------
// Kernel 1: normalize -> [B][L][C] K-major, fp16. Fully-unrolled c-loops
// for max MLP on the strided global loads.
// ---------------------------------------------------------------------------
__global__ void __launch_bounds__(256) norm_kernel(const float* __restrict__ trg,
                                                   const float* __restrict__ src,
                                                   const float* __restrict__ ref) {
    const int which = blockIdx.z;
    const float* x = (which == 0) ? trg : (which == 1) ? src : ref;
    __half* y      = (which == 0) ? g_q : (which == 1) ? g_ks : g_kr;

    const int b = blockIdx.y;
    const int l0 = blockIdx.x * 32;
    const int t = threadIdx.x;
    const int l = t & 31;
    const int cg = t >> 5;

    __shared__ float buf[32][257];
    __shared__ float red[2][8][32];
    __shared__ float mi[2][32];

    const float* xb = x + (size_t)b * NC * NL + l0 + l;

    float s = 0.f, q = 0.f;
#pragma unroll
    for (int cc = 0; cc < 32; cc++) {
        const int c = cg * 32 + cc;
        float v = xb[(size_t)c * NL];
        buf[l][c] = v;
        s += v;
        q += v * v;
    }
    red[0][cg][l] = s;
    red[1][cg][l] = q;
    __syncthreads();

    if (t < 32) {
        float su = 0.f, ss = 0.f;
#pragma unroll
        for (int w = 0; w < 8; w++) { su += red[0][w][t]; ss += red[1][w][t]; }
        const float mean = su * (1.0f / NC);
        mi[0][t] = mean;
        mi[1][t] = rsqrtf(fmaxf(ss - su * mean, 1e-30f));
    }
    __syncthreads();

    const float mean = mi[0][l];
    const float inv = mi[1][l];
#pragma unroll
    for (int cc = 0; cc < 32; cc++) {
        const int c = cg * 32 + cc;
        buf[l][c] = (buf[l][c] - mean) * inv;
    }
    __syncthreads();

    __half* yb = y + (size_t)b * NL * NC + (size_t)l0 * NC;
#pragma unroll
    for (int r = 0; r < 32; r += 4) {
        const __half h0 = __float2half_rn(buf[r + 0][t]);
        const __half h1 = __float2half_rn(buf[r + 1][t]);
        const __half h2 = __float2half_rn(buf[r + 2][t]);
        const __half h3 = __float2half_rn(buf[r + 3][t]);
        yb[(size_t)(r + 0) * NC + t] = h0;
        yb[(size_t)(r + 1) * NC + t] = h1;
        yb[(size_t)(r + 2) * NC + t] = h2;
        yb[(size_t)(r + 3) * NC + t] = h3;
    }
}

// ---------------------------------------------------------------------------
// Kernel 1b: padded fp16 V banks, flat valid-only grid + float4 loads.
// y mapping: [0,160) z=2 ; [160,320) z=3 ; [320,336) z=0 ; [336,352) z=1.
// ---------------------------------------------------------------------------
__global__ void __launch_bounds__(256) vprep_kernel(const float* __restrict__ sf,
                                                    const float* __restrict__ rf,
                                                    const float* __restrict__ rs) {
    const int y = blockIdx.y;
    int z, n;
    if (y < 160)      { z = 2; n = y; }
    else if (y < 320) { z = 3; n = y - 160; }
    else if (y < 336) { z = 0; n = y - 320; }
    else              { z = 1; n = y - 336; }
    const int b = z & 1, type = z >> 1;
    const int l = (blockIdx.x * 256 + threadIdx.x) * 4;

    float4 v = make_float4(0.f, 0.f, 0.f, 0.f);
    if (n < 4) v = *(const float4*)&((type ? rf : sf)[(size_t)b * 4 * NL + (size_t)n * NL + l]);
    else if (type && n < 155) v = *(const float4*)&rs[(size_t)b * 151 * NL + (size_t)(n - 4) * NL + l];

    const __half2 h0 = __floats2half2_rn(v.x, v.y);
    const __half2 h1 = __floats2half2_rn(v.z, v.w);
    __half2* dst = (__half2*)&g_v[(size_t)z * 160 * NL + (size_t)n * NL + l];
    dst[0] = h0;
    dst[1] = h1;
}

// ---------------------------------------------------------------------------
// Fused attention, j-split (type1 H=2 / 32 tiles; type0 H=8 / 8 tiles):
// each CTA = 128 Q-rows x NTILES j-tiles of 64. Q fragments register-
// resident. Partial O (fp32) + partial rsum to scratch; combine divides.
// ---------------------------------------------------------------------------
#define QOFF   0u
#define KOFF   65536u
#define KSTG   32768u
#define VOFF   (65536u + 3u * 32768u)       // 163840
#define ATTN_SMEM (163840 + 3 * 160 * 128)  // 225280

extern __shared__ char g_dsm[];

template <int TYPE, int NCH, int NTILES>
__device__ __forceinline__ void attn_body(int b, int i0, int h) {
    constexpr int NT2 = NCH / 16;
    constexpr int NO  = NCH / 8;
    constexpr uint32_t VSZ = NCH * 128;

    const int tid = threadIdx.x, lane = tid & 31, w = tid >> 5;
    const int z = TYPE * 2 + b;
    const int jbase = h * (NTILES * 64);

    const __half* __restrict__ Qp = g_q + (size_t)b * NL * NC;
    const __half* __restrict__ Kp = (TYPE ? g_kr : g_ks) + (size_t)b * NL * NC;
    const __half* __restrict__ Vp = g_v + (size_t)z * 160 * NL;

    const uint32_t sb = smem_u32(g_dsm);

    auto load_q = [&]() {
#pragma unroll
        for (int it = 0; it < 16; it++) {
            int idx = tid + it * 256;
            int m = idx >> 5, rem = idx & 31, kb = rem >> 3, f = rem & 7;
            CPA16(sb + QOFF + kb * 16384u + swzb(m, f),
                  Qp + (size_t)(i0 + m) * NC + kb * 64 + f * 8);
        }
    };
    auto stage_kv = [&](int st, int j0) {
        const uint32_t kbase = sb + KOFF + (uint32_t)st * KSTG;
#pragma unroll
        for (int it = 0; it < 8; it++) {
            int idx = tid + it * 256;
            int m = idx >> 5, rem = idx & 31, kb = rem >> 3, f = rem & 7;
            CPA16(kbase + kb * 8192u + swzb(m, f),
                  Kp + (size_t)(j0 + m) * NC + kb * 64 + f * 8);
        }
        const uint32_t vbase = sb + VOFF + (uint32_t)st * VSZ;
        for (int idx = tid; idx < NCH * 8; idx += 256) {
            int n = idx >> 3, f = idx & 7;
            CPA16(vbase + swzb(n, f), Vp + (size_t)n * NL + j0 + f * 8);
        }
    };

    const int arow = ((lane >> 3) & 1) * 8 + (lane & 7);
    const int a_fb = lane >> 4;
    const int m_row = w * 16 + arow;
    const uint32_t a_off = (uint32_t)m_row << 7;
    const int a_x = arow & 7;

    const int brow = ((lane >> 4) & 1) * 8 + (lane & 7);
    const int b_fb = (lane >> 3) & 1;
    const uint32_t b_off = (uint32_t)brow << 7;
    const int b_x = brow & 7;

    float oacc[NO][4];
#pragma unroll
    for (int nt = 0; nt < NO; nt++)
#pragma unroll
        for (int k = 0; k < 4; k++) oacc[nt][k] = 0.f;
    float rs0 = 0.f, rs1 = 0.f;

    load_q();
    stage_kv(0, jbase);
    CPCOMMIT();
    stage_kv(1, jbase + 64);
    CPCOMMIT();

    // ---- wait for Q (+stage0) and hoist all Q fragments into registers ----
    CPWAIT(1);
    __syncthreads();
    uint32_t qf[16][4];
#pragma unroll
    for (int ks = 0; ks < 16; ks++) {
        const int kb = ks >> 2, ff = (ks & 3) * 2;
        const int f = ff + a_fb;
        LDSM_X4(qf[ks][0], qf[ks][1], qf[ks][2], qf[ks][3],
                sb + QOFF + kb * 16384u + a_off + (uint32_t)((f ^ a_x) << 4));
    }

    int buf = 0;
    for (int c = 0; c < NTILES; c++) {
        if (c > 0) {
            if (c < NTILES - 1) { CPWAIT(1); } else { CPWAIT(0); }
            __syncthreads();
        }
        const uint32_t Kb = sb + KOFF + (uint32_t)buf * KSTG;
        const uint32_t Vb = sb + VOFF + (uint32_t)buf * VSZ;

        // ---- S = Q K^T over K=256 (A-frags resident) ----
        float s[8][4];
#pragma unroll
        for (int nt = 0; nt < 8; nt++)
#pragma unroll
            for (int k = 0; k < 4; k++) s[nt][k] = 0.f;

#pragma unroll
        for (int ks = 0; ks < 16; ks++) {
            const int kb = ks >> 2, ff = (ks & 3) * 2;
#pragma unroll
            for (int nt2 = 0; nt2 < 4; nt2++) {
                uint32_t bb[4];
                const int f = ff + b_fb;
                LDSM_X4(bb[0], bb[1], bb[2], bb[3],
                        Kb + kb * 8192u + (uint32_t)(nt2 << 11) + b_off + (uint32_t)((f ^ b_x) << 4));
                mma16(s[nt2 * 2],     qf[ks], bb[0], bb[1]);
                mma16(s[nt2 * 2 + 1], qf[ks], bb[2], bb[3]);
            }
        }

        // ---- exp (folded into PV per kk-group) + PV ----
#pragma unroll
        for (int kk = 0; kk < 4; kk++) {
            const float e00 = __expf(s[2 * kk][0]);
            const float e01 = __expf(s[2 * kk][1]);
            const float e02 = __expf(s[2 * kk][2]);
            const float e03 = __expf(s[2 * kk][3]);
            const float e10 = __expf(s[2 * kk + 1][0]);
            const float e11 = __expf(s[2 * kk + 1][1]);
            const float e12 = __expf(s[2 * kk + 1][2]);
            const float e13 = __expf(s[2 * kk + 1][3]);
            rs0 += e00 + e01 + e10 + e11;
            rs1 += e02 + e03 + e12 + e13;

            uint32_t af[4];
            {
                __half2 hh2;
                hh2 = __floats2half2_rn(e00, e01); af[0] = *(uint32_t*)&hh2;
                hh2 = __floats2half2_rn(e02, e03); af[1] = *(uint32_t*)&hh2;
                hh2 = __floats2half2_rn(e10, e11); af[2] = *(uint32_t*)&hh2;
                hh2 = __floats2half2_rn(e12, e13); af[3] = *(uint32_t*)&hh2;
            }
#pragma unroll
            for (int nt2 = 0; nt2 < NT2; nt2++) {
                uint32_t bb[4];
                const int f = 2 * kk + b_fb;
                LDSM_X4(bb[0], bb[1], bb[2], bb[3],
                        Vb + (uint32_t)(nt2 << 11) + b_off + (uint32_t)((f ^ b_x) << 4));
                mma16(oacc[nt2 * 2],     af, bb[0], bb[1]);
                mma16(oacc[nt2 * 2 + 1], af, bb[2], bb[3]);
            }
        }

        if (c < NTILES - 2) {
            int nb = buf + 2; if (nb >= 3) nb -= 3;
            stage_kv(nb, jbase + (c + 2) * 64);
            CPCOMMIT();
        }
        if (++buf == 3) buf = 0;
    }

    // ---- epilogue: write partial O and partial rsum ----
    const int q = lane & 3, r = lane >> 2;
    rs0 += __shfl_xor_sync(0xffffffffu, rs0, 1);
    rs0 += __shfl_xor_sync(0xffffffffu, rs0, 2);
    rs1 += __shfl_xor_sync(0xffffffffu, rs1, 1);
    rs1 += __shfl_xor_sync(0xffffffffu, rs1, 2);

    const int row = i0 + w * 16 + r;
    const int zh = z * 8 + h;
    if (q == 0) {
        g_rsp[(size_t)zh * NL + row]     = rs0;
        g_rsp[(size_t)zh * NL + row + 8] = rs1;
    }

    float* Op = g_opart + (size_t)zh * 160 * NL;
#pragma unroll
    for (int nt = 0; nt < NO; nt++) {
        const int cbase = nt * 8 + 2 * q;
#pragma unroll
        for (int hh = 0; hh < 2; hh++) {
            const int i = row + hh * 8;
#pragma unroll
            for (int dd = 0; dd < 2; dd++) {
                Op[(size_t)(cbase + dd) * NL + i] = oacc[nt][hh * 2 + dd];
            }
        }
    }
}

// type1 first (long jobs, H=2): 128 CTAs; then type0 (H=8): 512 CTAs.
__global__ void __launch_bounds__(256, 1) attn_kernel() {
    const int tt = blockIdx.x;
    if (tt < 128) {
        attn_body<1, 160, 32>(tt >> 6, ((tt >> 1) & 31) * 128, tt & 1);
    } else {
        const int u = tt - 128;   // u in [0,512): b(1) x i(32) x h(8)
        attn_body<0, 16, 8>(u >> 8, ((u >> 3) & 31) * 128, u & 7);
    }
}

// ---------------------------------------------------------------------------
// Combine: out = (sum_h O_h) / (sum_h rs_h). Flat valid-only grid, one
// float4 chunk per thread (round-12 shape: more blocks, better latency
// hiding at moderate occupancy). H: type1=2, type0=8.
// y mapping: [0,155) z=2 ; [155,310) z=3 ; [310,314) z=0 ; [314,318) z=1.
// ---------------------------------------------------------------------------
__global__ void __launch_bounds__(256) combine_kernel(float* __restrict__ out) {
    const int y = blockIdx.y;
    int z, ch;
    if (y < 155)      { z = 2; ch = y; }
    else if (y < 310) { z = 3; ch = y - 155; }
    else if (y < 314) { z = 0; ch = y - 310; }
    else              { z = 1; ch = y - 314; }
    const int b = z & 1, type = z >> 1;
    const int H = type ? 2 : 8;
    const int i = (blockIdx.x * 256 + threadIdx.x) * 4;

    float4 rs = make_float4(0.f, 0.f, 0.f, 0.f);
    float4 o  = make_float4(0.f, 0.f, 0.f, 0.f);
    for (int h = 0; h < H; h++) {
        const float4 r4 = *(const float4*)&g_rsp[(size_t)(z * 8 + h) * NL + i];
        const float4 o4 = *(const float4*)&g_opart[((size_t)(z * 8 + h) * 160 + ch) * NL + i];
        rs.x += r4.x; rs.y += r4.y; rs.z += r4.z; rs.w += r4.w;
        o.x += o4.x; o.y += o4.y; o.z += o4.z; o.w += o4.w;
    }
    const float4 val = make_float4(o.x / rs.x, o.y / rs.y, o.z / rs.z, o.w / rs.w);

    float* dst;
    if (ch < 4) {
        float* Of = type ? (out + 2 * 4 * NL + (size_t)b * 4 * NL)
                         : (out + (size_t)b * 4 * NL);
        dst = &Of[(size_t)ch * NL + i];
    } else {
        float* Os = out + 4 * 4 * NL + (size_t)b * 151 * NL;
        dst = &Os[(size_t)(ch - 4) * NL + i];
    }
    *(float4*)dst = val;
}

// ---------------------------------------------------------------------------
extern "C" void kernel_launch(void* const* d_in, const int* in_sizes, int n_in,
                              void* d_out, int out_size) {
    const float* trg       = (const float*)d_in[0];
    const float* src       = (const float*)d_in[1];
    const float* ref       = (const float*)d_in[2];
    const float* src_feats = (const float*)d_in[3];
    const float* ref_feats = (const float*)d_in[4];
    const float* ref_sem   = (const float*)d_in[5];
    float* out = (float*)d_out;

    cudaFuncSetAttribute(attn_kernel, cudaFuncAttributeMaxDynamicSharedMemorySize, ATTN_SMEM);

    norm_kernel<<<dim3(NL / 32, NB, 3), 256>>>(trg, src, ref);
    vprep_kernel<<<dim3(NL / 1024, 352), 256>>>(src_feats, ref_feats, ref_sem);
    attn_kernel<<<640, 256, ATTN_SMEM>>>();
    combine_kernel<<<dim3(NL / 1024, 318), 256>>>(out);
}

// round 16
// speedup vs baseline: 1.0075x; 1.0075x over previous
#include <cuda_runtime.h>
#include <cuda_fp16.h>
#include <cstdint>

#define NB 2
#define NC 256
#define NL 4096

// ---------------------------------------------------------------------------
// Scratch
// ---------------------------------------------------------------------------
__device__ __half g_q [NB * NL * NC];       // normalized trg, [B][L][C] K-major
__device__ __half g_ks[NB * NL * NC];
__device__ __half g_kr[NB * NL * NC];
__device__ __half g_v [4ull * 160 * NL];    // padded V banks per z
__device__ float  g_opart[4ull * 8 * 160 * NL];  // partial O [z][h<8][ch][i]
__device__ float  g_rsp  [4 * 8 * NL];           // partial rsum [z][h][i]

// ---------------------------------------------------------------------------
// helpers
// ---------------------------------------------------------------------------
__device__ __forceinline__ uint32_t smem_u32(const void* p) {
    uint32_t a;
    asm("{ .reg .u64 t; cvta.to.shared.u64 t, %1; cvt.u32.u64 %0, t; }" : "=r"(a) : "l"(p));
    return a;
}

#define CPA16(dst, src) asm volatile("cp.async.cg.shared.global [%0], [%1], 16;" :: "r"(dst), "l"(src))
#define CPCOMMIT()      asm volatile("cp.async.commit_group;" ::: "memory")
#define CPWAIT(n)       asm volatile("cp.async.wait_group %0;" :: "n"(n) : "memory")

#define LDSM_X4(R0, R1, R2, R3, A) \
    asm volatile("ldmatrix.sync.aligned.m8n8.x4.shared.b16 {%0,%1,%2,%3}, [%4];" \
                 : "=r"(R0), "=r"(R1), "=r"(R2), "=r"(R3) : "r"(A))

// byte offset of the 16B group (m, f) in a 128B-row tile, row-XOR swizzled
__device__ __forceinline__ uint32_t swzb(int m, int f) {
    return ((uint32_t)m << 7) + (uint32_t)(((f) ^ (m & 7)) << 4);
}

__device__ __forceinline__ void mma16(float* d, const uint32_t* a, uint32_t b0, uint32_t b1) {
    asm volatile(
        "mma.sync.aligned.m16n8k16.row.col.f32.f16.f16.f32 "
        "{%0,%1,%2,%3}, {%4,%5,%6,%7}, {%8,%9}, {%0,%1,%2,%3};"
        : "+f"(d[0]), "+f"(d[1]), "+f"(d[2]), "+f"(d[3])
        : "r"(a[0]), "r"(a[1]), "r"(a[2]), "r"(a[3]), "r"(b0), "r"(b1));
}

// ---------------------------------------------------------------------------
// Kernel 1: normalize -> [B][L][C] K-major, fp16.
// Phase 1: float4 loads across l (8x LDG.128/thread), per-quad partial sums.
// Phase 2: column reduce. Phase 3: fused scale + transposed fp16 write.
// ---------------------------------------------------------------------------
__global__ void __launch_bounds__(256) norm_kernel(const float* __restrict__ trg,
                                                   const float* __restrict__ src,
                                                   const float* __restrict__ ref) {
    const int which = blockIdx.z;
    const float* x = (which == 0) ? trg : (which == 1) ? src : ref;
    __half* y      = (which == 0) ? g_q : (which == 1) ? g_ks : g_kr;

    const int b = blockIdx.y;
    const int l0 = blockIdx.x * 32;
    const int t = threadIdx.x;
    const int lq = t & 7;          // l-quad: covers l = lq*4 .. lq*4+3
    const int cg = t >> 3;         // 0..31: c-group, c = cg + it*32

    __shared__ float buf[32][257];     // [l][c]
    __shared__ float reds[32][33];     // partial sums  [cg][l]
    __shared__ float redq[32][33];     // partial sumsq [cg][l]
    __shared__ float mi[2][32];

    const float* xb = x + (size_t)b * NC * NL + l0 + lq * 4;

    float4 s4 = make_float4(0.f, 0.f, 0.f, 0.f);
    float4 q4 = make_float4(0.f, 0.f, 0.f, 0.f);
#pragma unroll
    for (int it = 0; it < 8; it++) {
        const int c = cg + it * 32;
        const float4 v = *(const float4*)(xb + (size_t)c * NL);
        buf[lq * 4 + 0][c] = v.x;
        buf[lq * 4 + 1][c] = v.y;
        buf[lq * 4 + 2][c] = v.z;
        buf[lq * 4 + 3][c] = v.w;
        s4.x += v.x; s4.y += v.y; s4.z += v.z; s4.w += v.w;
        q4.x = fmaf(v.x, v.x, q4.x);
        q4.y = fmaf(v.y, v.y, q4.y);
        q4.z = fmaf(v.z, v.z, q4.z);
        q4.w = fmaf(v.w, v.w, q4.w);
    }
    reds[cg][lq * 4 + 0] = s4.x;
    reds[cg][lq * 4 + 1] = s4.y;
    reds[cg][lq * 4 + 2] = s4.z;
    reds[cg][lq * 4 + 3] = s4.w;
    redq[cg][lq * 4 + 0] = q4.x;
    redq[cg][lq * 4 + 1] = q4.y;
    redq[cg][lq * 4 + 2] = q4.z;
    redq[cg][lq * 4 + 3] = q4.w;
    __syncthreads();

    if (t < 32) {
        float su = 0.f, ss = 0.f;
#pragma unroll
        for (int g = 0; g < 32; g++) { su += reds[g][t]; ss += redq[g][t]; }
        const float mean = su * (1.0f / NC);
        mi[0][t] = mean;
        mi[1][t] = rsqrtf(fmaxf(ss - su * mean, 1e-30f));
    }
    __syncthreads();

    // fused scale + transposed fp16 write: thread t = channel, rows r = l
    __half* yb = y + (size_t)b * NL * NC + (size_t)l0 * NC;
#pragma unroll
    for (int r = 0; r < 32; r += 4) {
        const float v0 = (buf[r + 0][t] - mi[0][r + 0]) * mi[1][r + 0];
        const float v1 = (buf[r + 1][t] - mi[0][r + 1]) * mi[1][r + 1];
        const float v2 = (buf[r + 2][t] - mi[0][r + 2]) * mi[1][r + 2];
        const float v3 = (buf[r + 3][t] - mi[0][r + 3]) * mi[1][r + 3];
        yb[(size_t)(r + 0) * NC + t] = __float2half_rn(v0);
        yb[(size_t)(r + 1) * NC + t] = __float2half_rn(v1);
        yb[(size_t)(r + 2) * NC + t] = __float2half_rn(v2);
        yb[(size_t)(r + 3) * NC + t] = __float2half_rn(v3);
    }
}

// ---------------------------------------------------------------------------
// Kernel 1b: padded fp16 V banks, flat valid-only grid + float4 loads.
// y mapping: [0,160) z=2 ; [160,320) z=3 ; [320,336) z=0 ; [336,352) z=1.
// ---------------------------------------------------------------------------
__global__ void __launch_bounds__(256) vprep_kernel(const float* __restrict__ sf,
                                                    const float* __restrict__ rf,
                                                    const float* __restrict__ rs) {
    const int y = blockIdx.y;
    int z, n;
    if (y < 160)      { z = 2; n = y; }
    else if (y < 320) { z = 3; n = y - 160; }
    else if (y < 336) { z = 0; n = y - 320; }
    else              { z = 1; n = y - 336; }
    const int b = z & 1, type = z >> 1;
    const int l = (blockIdx.x * 256 + threadIdx.x) * 4;

    float4 v = make_float4(0.f, 0.f, 0.f, 0.f);
    if (n < 4) v = *(const float4*)&((type ? rf : sf)[(size_t)b * 4 * NL + (size_t)n * NL + l]);
    else if (type && n < 155) v = *(const float4*)&rs[(size_t)b * 151 * NL + (size_t)(n - 4) * NL + l];

    const __half2 h0 = __floats2half2_rn(v.x, v.y);
    const __half2 h1 = __floats2half2_rn(v.z, v.w);
    __half2* dst = (__half2*)&g_v[(size_t)z * 160 * NL + (size_t)n * NL + l];
    dst[0] = h0;
    dst[1] = h1;
}

// ---------------------------------------------------------------------------
// Fused attention, j-split (type1 H=2 / 32 tiles; type0 H=8 / 8 tiles):
// each CTA = 128 Q-rows x NTILES j-tiles of 64. Q fragments register-
// resident. Partial O (fp32) + partial rsum to scratch; combine divides.
// ---------------------------------------------------------------------------
#define QOFF   0u
#define KOFF   65536u
#define KSTG   32768u
#define VOFF   (65536u + 3u * 32768u)       // 163840
#define ATTN_SMEM (163840 + 3 * 160 * 128)  // 225280

extern __shared__ char g_dsm[];

template <int TYPE, int NCH, int NTILES>
__device__ __forceinline__ void attn_body(int b, int i0, int h) {
    constexpr int NT2 = NCH / 16;
    constexpr int NO  = NCH / 8;
    constexpr uint32_t VSZ = NCH * 128;

    const int tid = threadIdx.x, lane = tid & 31, w = tid >> 5;
    const int z = TYPE * 2 + b;
    const int jbase = h * (NTILES * 64);

    const __half* __restrict__ Qp = g_q + (size_t)b * NL * NC;
    const __half* __restrict__ Kp = (TYPE ? g_kr : g_ks) + (size_t)b * NL * NC;
    const __half* __restrict__ Vp = g_v + (size_t)z * 160 * NL;

    const uint32_t sb = smem_u32(g_dsm);

    auto load_q = [&]() {
#pragma unroll
        for (int it = 0; it < 16; it++) {
            int idx = tid + it * 256;
            int m = idx >> 5, rem = idx & 31, kb = rem >> 3, f = rem & 7;
            CPA16(sb + QOFF + kb * 16384u + swzb(m, f),
                  Qp + (size_t)(i0 + m) * NC + kb * 64 + f * 8);
        }
    };
    auto stage_kv = [&](int st, int j0) {
        const uint32_t kbase = sb + KOFF + (uint32_t)st * KSTG;
#pragma unroll
        for (int it = 0; it < 8; it++) {
            int idx = tid + it * 256;
            int m = idx >> 5, rem = idx & 31, kb = rem >> 3, f = rem & 7;
            CPA16(kbase + kb * 8192u + swzb(m, f),
                  Kp + (size_t)(j0 + m) * NC + kb * 64 + f * 8);
        }
        const uint32_t vbase = sb + VOFF + (uint32_t)st * VSZ;
        for (int idx = tid; idx < NCH * 8; idx += 256) {
            int n = idx >> 3, f = idx & 7;
            CPA16(vbase + swzb(n, f), Vp + (size_t)n * NL + j0 + f * 8);
        }
    };

    const int arow = ((lane >> 3) & 1) * 8 + (lane & 7);
    const int a_fb = lane >> 4;
    const int m_row = w * 16 + arow;
    const uint32_t a_off = (uint32_t)m_row << 7;
    const int a_x = arow & 7;

    const int brow = ((lane >> 4) & 1) * 8 + (lane & 7);
    const int b_fb = (lane >> 3) & 1;
    const uint32_t b_off = (uint32_t)brow << 7;
    const int b_x = brow & 7;

    float oacc[NO][4];
#pragma unroll
    for (int nt = 0; nt < NO; nt++)
#pragma unroll
        for (int k = 0; k < 4; k++) oacc[nt][k] = 0.f;
    float rs0 = 0.f, rs1 = 0.f;

    load_q();
    stage_kv(0, jbase);
    CPCOMMIT();
    stage_kv(1, jbase + 64);
    CPCOMMIT();

    // ---- wait for Q (+stage0) and hoist all Q fragments into registers ----
    CPWAIT(1);
    __syncthreads();
    uint32_t qf[16][4];
#pragma unroll
    for (int ks = 0; ks < 16; ks++) {
        const int kb = ks >> 2, ff = (ks & 3) * 2;
        const int f = ff + a_fb;
        LDSM_X4(qf[ks][0], qf[ks][1], qf[ks][2], qf[ks][3],
                sb + QOFF + kb * 16384u + a_off + (uint32_t)((f ^ a_x) << 4));
    }

    int buf = 0;
    for (int c = 0; c < NTILES; c++) {
        if (c > 0) {
            if (c < NTILES - 1) { CPWAIT(1); } else { CPWAIT(0); }
            __syncthreads();
        }
        const uint32_t Kb = sb + KOFF + (uint32_t)buf * KSTG;
        const uint32_t Vb = sb + VOFF + (uint32_t)buf * VSZ;

        // ---- S = Q K^T over K=256 (A-frags resident) ----
        float s[8][4];
#pragma unroll
        for (int nt = 0; nt < 8; nt++)
#pragma unroll
            for (int k = 0; k < 4; k++) s[nt][k] = 0.f;

#pragma unroll
        for (int ks = 0; ks < 16; ks++) {
            const int kb = ks >> 2, ff = (ks & 3) * 2;
#pragma unroll
            for (int nt2 = 0; nt2 < 4; nt2++) {
                uint32_t bb[4];
                const int f = ff + b_fb;
                LDSM_X4(bb[0], bb[1], bb[2], bb[3],
                        Kb + kb * 8192u + (uint32_t)(nt2 << 11) + b_off + (uint32_t)((f ^ b_x) << 4));
                mma16(s[nt2 * 2],     qf[ks], bb[0], bb[1]);
                mma16(s[nt2 * 2 + 1], qf[ks], bb[2], bb[3]);
            }
        }

        // ---- exp (folded into PV per kk-group) + PV ----
#pragma unroll
        for (int kk = 0; kk < 4; kk++) {
            const float e00 = __expf(s[2 * kk][0]);
            const float e01 = __expf(s[2 * kk][1]);
            const float e02 = __expf(s[2 * kk][2]);
            const float e03 = __expf(s[2 * kk][3]);
            const float e10 = __expf(s[2 * kk + 1][0]);
            const float e11 = __expf(s[2 * kk + 1][1]);
            const float e12 = __expf(s[2 * kk + 1][2]);
            const float e13 = __expf(s[2 * kk + 1][3]);
            rs0 += e00 + e01 + e10 + e11;
            rs1 += e02 + e03 + e12 + e13;

            uint32_t af[4];
            {
                __half2 hh2;
                hh2 = __floats2half2_rn(e00, e01); af[0] = *(uint32_t*)&hh2;
                hh2 = __floats2half2_rn(e02, e03); af[1] = *(uint32_t*)&hh2;
                hh2 = __floats2half2_rn(e10, e11); af[2] = *(uint32_t*)&hh2;
                hh2 = __floats2half2_rn(e12, e13); af[3] = *(uint32_t*)&hh2;
            }
#pragma unroll
            for (int nt2 = 0; nt2 < NT2; nt2++) {
                uint32_t bb[4];
                const int f = 2 * kk + b_fb;
                LDSM_X4(bb[0], bb[1], bb[2], bb[3],
                        Vb + (uint32_t)(nt2 << 11) + b_off + (uint32_t)((f ^ b_x) << 4));
                mma16(oacc[nt2 * 2],     af, bb[0], bb[1]);
                mma16(oacc[nt2 * 2 + 1], af, bb[2], bb[3]);
            }
        }

        if (c < NTILES - 2) {
            int nb = buf + 2; if (nb >= 3) nb -= 3;
            stage_kv(nb, jbase + (c + 2) * 64);
            CPCOMMIT();
        }
        if (++buf == 3) buf = 0;
    }

    // ---- epilogue: write partial O and partial rsum ----
    const int q = lane & 3, r = lane >> 2;
    rs0 += __shfl_xor_sync(0xffffffffu, rs0, 1);
    rs0 += __shfl_xor_sync(0xffffffffu, rs0, 2);
    rs1 += __shfl_xor_sync(0xffffffffu, rs1, 1);
    rs1 += __shfl_xor_sync(0xffffffffu, rs1, 2);

    const int row = i0 + w * 16 + r;
    const int zh = z * 8 + h;
    if (q == 0) {
        g_rsp[(size_t)zh * NL + row]     = rs0;
        g_rsp[(size_t)zh * NL + row + 8] = rs1;
    }

    float* Op = g_opart + (size_t)zh * 160 * NL;
#pragma unroll
    for (int nt = 0; nt < NO; nt++) {
        const int cbase = nt * 8 + 2 * q;
#pragma unroll
        for (int hh = 0; hh < 2; hh++) {
            const int i = row + hh * 8;
#pragma unroll
            for (int dd = 0; dd < 2; dd++) {
                Op[(size_t)(cbase + dd) * NL + i] = oacc[nt][hh * 2 + dd];
            }
        }
    }
}

// type1 first (long jobs, H=2): 128 CTAs; then type0 (H=8): 512 CTAs.
__global__ void __launch_bounds__(256, 1) attn_kernel() {
    const int tt = blockIdx.x;
    if (tt < 128) {
        attn_body<1, 160, 32>(tt >> 6, ((tt >> 1) & 31) * 128, tt & 1);
    } else {
        const int u = tt - 128;   // u in [0,512): b(1) x i(32) x h(8)
        attn_body<0, 16, 8>(u >> 8, ((u >> 3) & 31) * 128, u & 7);
    }
}

// ---------------------------------------------------------------------------
// Combine: out = (sum_h O_h) / (sum_h rs_h). Flat valid-only grid, one
// float4 chunk per thread. H: type1=2, type0=8.
// y mapping: [0,155) z=2 ; [155,310) z=3 ; [310,314) z=0 ; [314,318) z=1.
// ---------------------------------------------------------------------------
__global__ void __launch_bounds__(256) combine_kernel(float* __restrict__ out) {
    const int y = blockIdx.y;
    int z, ch;
    if (y < 155)      { z = 2; ch = y; }
    else if (y < 310) { z = 3; ch = y - 155; }
    else if (y < 314) { z = 0; ch = y - 310; }
    else              { z = 1; ch = y - 314; }
    const int b = z & 1, type = z >> 1;
    const int H = type ? 2 : 8;
    const int i = (blockIdx.x * 256 + threadIdx.x) * 4;

    float4 rs = make_float4(0.f, 0.f, 0.f, 0.f);
    float4 o  = make_float4(0.f, 0.f, 0.f, 0.f);
    for (int h = 0; h < H; h++) {
        const float4 r4 = *(const float4*)&g_rsp[(size_t)(z * 8 + h) * NL + i];
        const float4 o4 = *(const float4*)&g_opart[((size_t)(z * 8 + h) * 160 + ch) * NL + i];
        rs.x += r4.x; rs.y += r4.y; rs.z += r4.z; rs.w += r4.w;
        o.x += o4.x; o.y += o4.y; o.z += o4.z; o.w += o4.w;
    }
    const float4 val = make_float4(o.x / rs.x, o.y / rs.y, o.z / rs.z, o.w / rs.w);

    float* dst;
    if (ch < 4) {
        float* Of = type ? (out + 2 * 4 * NL + (size_t)b * 4 * NL)
                         : (out + (size_t)b * 4 * NL);
        dst = &Of[(size_t)ch * NL + i];
    } else {
        float* Os = out + 4 * 4 * NL + (size_t)b * 151 * NL;
        dst = &Os[(size_t)(ch - 4) * NL + i];
    }
    *(float4*)dst = val;
}

// ---------------------------------------------------------------------------
extern "C" void kernel_launch(void* const* d_in, const int* in_sizes, int n_in,
                              void* d_out, int out_size) {
    const float* trg       = (const float*)d_in[0];
    const float* src       = (const float*)d_in[1];
    const float* ref       = (const float*)d_in[2];
    const float* src_feats = (const float*)d_in[3];
    const float* ref_feats = (const float*)d_in[4];
    const float* ref_sem   = (const float*)d_in[5];
    float* out = (float*)d_out;

    cudaFuncSetAttribute(attn_kernel, cudaFuncAttributeMaxDynamicSharedMemorySize, ATTN_SMEM);

    norm_kernel<<<dim3(NL / 32, NB, 3), 256>>>(trg, src, ref);
    vprep_kernel<<<dim3(NL / 1024, 352), 256>>>(src_feats, ref_feats, ref_sem);
    attn_kernel<<<640, 256, ATTN_SMEM>>>();
    combine_kernel<<<dim3(NL / 1024, 318), 256>>>(out);
}